// round 4
// baseline (speedup 1.0000x reference)
#include <cuda_runtime.h>
#include <math.h>

#define N_NODES 50000
#define N_EDGES 400000
#define F_DIM   128
#define N_TYPES 100
#define N_RBF   20
#define CUTOFF  5.0f
#define F3      (3 * F_DIM)   // 384

#define SCAN_B  256
#define SCAN_NB ((N_NODES + SCAN_B - 1) / SCAN_B)   // 196

typedef unsigned long long ull;

// -------- device scratch (no allocations allowed) --------
__device__ int   g_count[N_NODES];
__device__ int   g_start[N_NODES + 1];
__device__ int   g_cursor[N_NODES];
__device__ int   g_sorted[N_EDGES];
__device__ int   g_partial[SCAN_NB];
__device__ int   g_boff[SCAN_NB];
__device__ float g_phi[N_TYPES * F3];   // 100 x 384

// ---- packed f32x2 helpers ----
__device__ __forceinline__ ull pack2(float lo, float hi) {
    ull r;
    asm("mov.b64 %0, {%1, %2};" : "=l"(r) : "f"(lo), "f"(hi));
    return r;
}
__device__ __forceinline__ void unpack2(float& lo, float& hi, ull p) {
    asm("mov.b64 {%0, %1}, %2;" : "=f"(lo), "=f"(hi) : "l"(p));
}
__device__ __forceinline__ void ffma2(ull& d, ull a, ull b) {
    asm("fma.rn.f32x2 %0, %1, %2, %0;" : "+l"(d) : "l"(a), "l"(b));
}

// ---------------------------------------------------------
__global__ void zero_kernel() {
    int i = blockIdx.x * blockDim.x + threadIdx.x;
    if (i < N_NODES) g_count[i] = 0;
}

// ---------------------------------------------------------
// phi_type[t] = silu(emb_table[t] @ w1 + b1) @ w2 + b2   (100 x 384)
__global__ void phi_kernel(const float* __restrict__ emb_table,
                           const float* __restrict__ w1, const float* __restrict__ b1,
                           const float* __restrict__ w2, const float* __restrict__ b2) {
    int t = blockIdx.x;
    int f = threadIdx.x;
    __shared__ float es[F_DIM];
    __shared__ float hs[F_DIM];
    es[f] = emb_table[t * F_DIM + f];
    __syncthreads();
    float h = b1[f];
#pragma unroll 8
    for (int k = 0; k < F_DIM; k++)
        h = fmaf(es[k], w1[k * F_DIM + f], h);
    h = h / (1.0f + expf(-h));   // silu
    hs[f] = h;
    __syncthreads();
    float o0 = b2[f], o1 = b2[F_DIM + f], o2 = b2[2 * F_DIM + f];
#pragma unroll 8
    for (int k = 0; k < F_DIM; k++) {
        float hk = hs[k];
        const float* w2r = w2 + k * F3;
        o0 = fmaf(hk, w2r[f],             o0);
        o1 = fmaf(hk, w2r[F_DIM + f],     o1);
        o2 = fmaf(hk, w2r[2 * F_DIM + f], o2);
    }
    g_phi[t * F3 + f]             = o0;
    g_phi[t * F3 + F_DIM + f]     = o1;
    g_phi[t * F3 + 2 * F_DIM + f] = o2;
}

// ---------------------------------------------------------
__global__ void hist_kernel(const int* __restrict__ edge_dst) {
    int e = blockIdx.x * blockDim.x + threadIdx.x;
    if (e < N_EDGES) atomicAdd(&g_count[edge_dst[e]], 1);
}

// ---------------------------------------------------------
__global__ void scan1_kernel() {
    __shared__ int wsum[SCAN_B / 32];
    int t = threadIdx.x;
    int i = blockIdx.x * SCAN_B + t;
    int v = (i < N_NODES) ? g_count[i] : 0;
    for (int off = 16; off > 0; off >>= 1)
        v += __shfl_down_sync(0xffffffffu, v, off);
    if ((t & 31) == 0) wsum[t >> 5] = v;
    __syncthreads();
    if (t < SCAN_B / 32) {
        int s = wsum[t];
        for (int off = SCAN_B / 64; off > 0; off >>= 1)
            s += __shfl_down_sync(0xffu, s, off);
        if (t == 0) g_partial[blockIdx.x] = s;
    }
}

__global__ void scan2_kernel() {
    __shared__ int wsum[8];
    int t = threadIdx.x;
    int v = (t < SCAN_NB) ? g_partial[t] : 0;
    int orig = v;
    for (int off = 1; off < 32; off <<= 1) {
        int u = __shfl_up_sync(0xffffffffu, v, off);
        if ((t & 31) >= off) v += u;
    }
    if ((t & 31) == 31) wsum[t >> 5] = v;
    __syncthreads();
    if (t < 8) {
        int s = wsum[t];
        for (int off = 1; off < 8; off <<= 1) {
            int u = __shfl_up_sync(0xffu, s, off);
            if (t >= off) s += u;
        }
        wsum[t] = s;
    }
    __syncthreads();
    int warp = t >> 5;
    int incl = v + ((warp > 0) ? wsum[warp - 1] : 0);
    if (t < SCAN_NB) g_boff[t] = incl - orig;
    if (t == SCAN_NB - 1) g_start[N_NODES] = incl;
}

__global__ void scan3_kernel() {
    __shared__ int wsum[SCAN_B / 32];
    int t = threadIdx.x;
    int i = blockIdx.x * SCAN_B + t;
    int v = (i < N_NODES) ? g_count[i] : 0;
    int orig = v;
    for (int off = 1; off < 32; off <<= 1) {
        int u = __shfl_up_sync(0xffffffffu, v, off);
        if ((t & 31) >= off) v += u;
    }
    if ((t & 31) == 31) wsum[t >> 5] = v;
    __syncthreads();
    if (t < SCAN_B / 32) {
        int s = wsum[t];
        for (int off = 1; off < SCAN_B / 32; off <<= 1) {
            int u = __shfl_up_sync(0xffu, s, off);
            if (t >= off) s += u;
        }
        wsum[t] = s;
    }
    __syncthreads();
    int warp = t >> 5;
    int excl = v - orig + ((warp > 0) ? wsum[warp - 1] : 0) + g_boff[blockIdx.x];
    if (i < N_NODES) {
        g_start[i]  = excl;
        g_cursor[i] = excl;
    }
}

// ---------------------------------------------------------
__global__ void scatter_kernel(const int* __restrict__ edge_dst) {
    int e = blockIdx.x * blockDim.x + threadIdx.x;
    if (e < N_EDGES) {
        int p = atomicAdd(&g_cursor[edge_dst[e]], 1);
        g_sorted[p] = e;
    }
}

// ---------------------------------------------------------
// Main: one block (128 threads) per destination node. Thread f owns channel f.
// W matvec done with packed f32x2 FMAs: even/odd-k halves in one 64-bit acc.
__global__ __launch_bounds__(128, 4)
void main_kernel(const float* __restrict__ pos,
                 const float* __restrict__ eq,
                 const float* __restrict__ emb_table,
                 const float* __restrict__ w_rbf,
                 const float* __restrict__ b_rbf,
                 const int*   __restrict__ z,
                 const int*   __restrict__ edge_src,
                 float* __restrict__ out_emb,
                 float* __restrict__ out_eq) {
    int f = threadIdx.x;
    int node = blockIdx.x;

    int e0 = g_start[node];
    int e1 = __ldg(&g_start[node + 1]);
    int zi = __ldg(&z[node]);

    // packed weight pairs: wrXp[j] = (w_rbf[2j][col], w_rbf[2j+1][col])  -- 60 regs
    ull wr0p[N_RBF / 2], wr1p[N_RBF / 2], wr2p[N_RBF / 2];
#pragma unroll
    for (int j = 0; j < N_RBF / 2; j++) {
        const float* ra = w_rbf + (2 * j) * F3;
        const float* rb = w_rbf + (2 * j + 1) * F3;
        wr0p[j] = pack2(ra[f],             rb[f]);
        wr1p[j] = pack2(ra[F_DIM + f],     rb[F_DIM + f]);
        wr2p[j] = pack2(ra[2 * F_DIM + f], rb[2 * F_DIM + f]);
    }
    const ull br0p = pack2(b_rbf[f],             0.f);
    const ull br1p = pack2(b_rbf[F_DIM + f],     0.f);
    const ull br2p = pack2(b_rbf[2 * F_DIM + f], 0.f);

    __shared__ __align__(16) float sh_rbf[128][N_RBF];  // rows 80B -> 8B aligned
    __shared__ __align__(16) float sh_rd[128][4];       // padded: 8B-aligned pairs
    __shared__ int   sh_src[128];
    __shared__ int   sh_typ[128];
    __shared__ float sh_pos[3];

    int cnt = e1 - e0;

    if (f < 3) sh_pos[f] = pos[node * 3 + f];
    __syncthreads();
    const float pix = sh_pos[0], piy = sh_pos[1], piz = sh_pos[2];

    float acc0 = 0.f, aq0 = 0.f, aq1 = 0.f, aq2 = 0.f;

    for (int base = 0; base < cnt; base += 128) {
        int nch = min(128, cnt - base);
        // phase 1: one thread per edge: geometry + RBF
        if (f < nch) {
            int e = __ldg(&g_sorted[e0 + base + f]);
            int s = __ldg(&edge_src[e]);
            sh_src[f] = s;
            sh_typ[f] = __ldg(&z[s]);
            float rx = pix - __ldg(&pos[s * 3 + 0]);
            float ry = piy - __ldg(&pos[s * 3 + 1]);
            float rz = piz - __ldg(&pos[s * 3 + 2]);
            float dist = sqrtf(rx * rx + ry * ry + rz * rz);
            float inv  = 1.0f / dist;
            sh_rd[f][0] = rx * dist;
            sh_rd[f][1] = ry * dist;
            sh_rd[f][2] = rz * dist;
            float a = 3.14159265358979323846f * dist * (1.0f / CUTOFF);
            float s1, c1;
            sincosf(a, &s1, &c1);
            float twoc = 2.0f * c1;
            float sp = 0.0f, sc = s1;      // sin(0), sin(a)
#pragma unroll
            for (int k = 0; k < N_RBF; k++) {   // sin((k+1)a), stable Chebyshev recurrence
                sh_rbf[f][k] = sc * inv;
                float nx = twoc * sc - sp;
                sp = sc; sc = nx;
            }
        }
        __syncthreads();
        // phase 2: all 128 threads accumulate over the chunk's edges
#pragma unroll 2
        for (int e = 0; e < nch; e++) {
            const float* ph = g_phi + sh_typ[e] * F3;
            int s = sh_src[e];
            const float* eqs = eq + (size_t)s * F3 + f * 3;
            float p0 = __ldg(&ph[f]);
            float p1 = __ldg(&ph[F_DIM + f]);
            float p2 = __ldg(&ph[2 * F_DIM + f]);
            float eq0 = eqs[0], eq1 = eqs[1], eq2 = eqs[2];

            // packed matvec: 10 LDS.64 + 30 FFMA2
            const ull* rp = reinterpret_cast<const ull*>(sh_rbf[e]);
            ull W0p = br0p, W1p = br1p, W2p = br2p;
#pragma unroll
            for (int j = 0; j < N_RBF / 2; j++) {
                ull r2 = rp[j];            // (r[2j], r[2j+1]) broadcast
                ffma2(W0p, wr0p[j], r2);
                ffma2(W1p, wr1p[j], r2);
                ffma2(W2p, wr2p[j], r2);
            }
            float l0, h0, l1, h1, l2, h2;
            unpack2(l0, h0, W0p);
            unpack2(l1, h1, W1p);
            unpack2(l2, h2, W2p);
            float W0 = l0 + h0, W1 = l1 + h1, W2 = l2 + h2;

            float s1v = p1 * W1;
            float s2v = p2 * W2;
            acc0 = fmaf(p0, W0, acc0);
            aq0 = fmaf(eq0, s1v, fmaf(s2v, sh_rd[e][0], aq0));
            aq1 = fmaf(eq1, s1v, fmaf(s2v, sh_rd[e][1], aq1));
            aq2 = fmaf(eq2, s1v, fmaf(s2v, sh_rd[e][2], aq2));
        }
        __syncthreads();
    }

    // epilogue: out = input + delta, written exactly once
    out_emb[node * F_DIM + f] = emb_table[zi * F_DIM + f] + acc0;
    const float* ei = eq     + (size_t)node * F3 + f * 3;
    float*       oe = out_eq + (size_t)node * F3 + f * 3;
    oe[0] = ei[0] + aq0;
    oe[1] = ei[1] + aq1;
    oe[2] = ei[2] + aq2;
}

// ---------------------------------------------------------
extern "C" void kernel_launch(void* const* d_in, const int* in_sizes, int n_in,
                              void* d_out, int out_size) {
    const float* pos       = (const float*)d_in[0];
    const float* eq        = (const float*)d_in[1];
    const float* emb_table = (const float*)d_in[2];
    const float* w_phi1    = (const float*)d_in[3];
    const float* b_phi1    = (const float*)d_in[4];
    const float* w_phi2    = (const float*)d_in[5];
    const float* b_phi2    = (const float*)d_in[6];
    const float* w_rbf     = (const float*)d_in[7];
    const float* b_rbf     = (const float*)d_in[8];
    const int*   z         = (const int*)d_in[9];
    const int*   edge_src  = (const int*)d_in[10];
    const int*   edge_dst  = (const int*)d_in[11];

    float* out     = (float*)d_out;
    float* out_emb = out;                                  // [N, 128]
    float* out_eq  = out + (size_t)N_NODES * F_DIM;        // [N, 128, 3]

    zero_kernel<<<(N_NODES + 255) / 256, 256>>>();
    phi_kernel<<<N_TYPES, F_DIM>>>(emb_table, w_phi1, b_phi1, w_phi2, b_phi2);
    hist_kernel<<<(N_EDGES + 255) / 256, 256>>>(edge_dst);
    scan1_kernel<<<SCAN_NB, SCAN_B>>>();
    scan2_kernel<<<1, 256>>>();
    scan3_kernel<<<SCAN_NB, SCAN_B>>>();
    scatter_kernel<<<(N_EDGES + 255) / 256, 256>>>(edge_dst);
    main_kernel<<<N_NODES, 128>>>(pos, eq, emb_table, w_rbf, b_rbf, z, edge_src,
                                  out_emb, out_eq);
}

// round 5
// speedup vs baseline: 1.3462x; 1.3462x over previous
#include <cuda_runtime.h>
#include <math.h>

#define N_NODES 50000
#define N_EDGES 400000
#define F_DIM   128
#define N_TYPES 100
#define N_RBF   20
#define CUTOFF  5.0f
#define F3      (3 * F_DIM)   // 384

#define SCAN_B  256
#define SCAN_NB ((N_NODES + SCAN_B - 1) / SCAN_B)   // 196
#define ZERO_NB ((N_NODES + 127) / 128)             // 391

// -------- device scratch (no allocations allowed) --------
__device__ int   g_count[N_NODES];
__device__ int   g_start[N_NODES + 1];
__device__ int   g_cursor[N_NODES];
__device__ int   g_sorted[N_EDGES];
__device__ int   g_partial[SCAN_NB];
__device__ float g_phi[N_TYPES * F3];   // 100 x 384

// ---------------------------------------------------------
// Kernel A (fused): blocks [0, ZERO_NB) zero the histogram;
// blocks [ZERO_NB, ZERO_NB+N_TYPES) compute phi for one atom type each.
__global__ void init_kernel(const float* __restrict__ emb_table,
                            const float* __restrict__ w1, const float* __restrict__ b1,
                            const float* __restrict__ w2, const float* __restrict__ b2) {
    if (blockIdx.x < ZERO_NB) {
        int i = blockIdx.x * 128 + threadIdx.x;
        if (i < N_NODES) g_count[i] = 0;
        return;
    }
    int t = blockIdx.x - ZERO_NB;   // atom type
    int f = threadIdx.x;            // 0..127
    __shared__ float es[F_DIM];
    __shared__ float hs[F_DIM];
    es[f] = emb_table[t * F_DIM + f];
    __syncthreads();
    float h = b1[f];
#pragma unroll 8
    for (int k = 0; k < F_DIM; k++)
        h = fmaf(es[k], w1[k * F_DIM + f], h);
    h = h / (1.0f + expf(-h));   // silu
    hs[f] = h;
    __syncthreads();
    float o0 = b2[f], o1 = b2[F_DIM + f], o2 = b2[2 * F_DIM + f];
#pragma unroll 8
    for (int k = 0; k < F_DIM; k++) {
        float hk = hs[k];
        const float* w2r = w2 + k * F3;
        o0 = fmaf(hk, w2r[f],             o0);
        o1 = fmaf(hk, w2r[F_DIM + f],     o1);
        o2 = fmaf(hk, w2r[2 * F_DIM + f], o2);
    }
    g_phi[t * F3 + f]             = o0;
    g_phi[t * F3 + F_DIM + f]     = o1;
    g_phi[t * F3 + 2 * F_DIM + f] = o2;
}

// ---------------------------------------------------------
__global__ void hist_kernel(const int* __restrict__ edge_dst) {
    int e = blockIdx.x * blockDim.x + threadIdx.x;
    if (e < N_EDGES) atomicAdd(&g_count[edge_dst[e]], 1);
}

// ---------------------------------------------------------
// Scan stage 1: per-block partial sums of g_count
__global__ void scan1_kernel() {
    __shared__ int wsum[SCAN_B / 32];
    int t = threadIdx.x;
    int i = blockIdx.x * SCAN_B + t;
    int v = (i < N_NODES) ? g_count[i] : 0;
    for (int off = 16; off > 0; off >>= 1)
        v += __shfl_down_sync(0xffffffffu, v, off);
    if ((t & 31) == 0) wsum[t >> 5] = v;
    __syncthreads();
    if (t < SCAN_B / 32) {
        int s = wsum[t];
        for (int off = SCAN_B / 64; off > 0; off >>= 1)
            s += __shfl_down_sync(0xffu, s, off);
        if (t == 0) g_partial[blockIdx.x] = s;
    }
}

// ---------------------------------------------------------
// Scan stage 2+3 fused: each block re-reduces the 196 partials to get its own
// block offset (and block 0 also the grand total), then does its local
// exclusive scan -> g_start, g_cursor.
__global__ void scan23_kernel() {
    __shared__ int wsum[SCAN_B / 32];
    __shared__ int s_boff, s_total;
    int t = threadIdx.x;

    // reduce partials[j] for j < blockIdx.x (block offset) and all j (total)
    {
        int p = (t < SCAN_NB) ? g_partial[t] : 0;
        int vm = (t < (int)blockIdx.x) ? p : 0;   // masked for offset
        int va = p;                                // all, for total
        for (int off = 16; off > 0; off >>= 1) {
            vm += __shfl_down_sync(0xffffffffu, vm, off);
            va += __shfl_down_sync(0xffffffffu, va, off);
        }
        __shared__ int wm[SCAN_B / 32], wa[SCAN_B / 32];
        if ((t & 31) == 0) { wm[t >> 5] = vm; wa[t >> 5] = va; }
        __syncthreads();
        if (t == 0) {
            int sm = 0, sa = 0;
#pragma unroll
            for (int w = 0; w < SCAN_B / 32; w++) { sm += wm[w]; sa += wa[w]; }
            s_boff = sm; s_total = sa;
        }
        __syncthreads();
    }
    if (blockIdx.x == 0 && t == 0) g_start[N_NODES] = s_total;

    // local exclusive scan of this block's 256 counts
    int i = blockIdx.x * SCAN_B + t;
    int v = (i < N_NODES) ? g_count[i] : 0;
    int orig = v;
    for (int off = 1; off < 32; off <<= 1) {
        int u = __shfl_up_sync(0xffffffffu, v, off);
        if ((t & 31) >= off) v += u;
    }
    if ((t & 31) == 31) wsum[t >> 5] = v;
    __syncthreads();
    if (t < SCAN_B / 32) {
        int s = wsum[t];
        for (int off = 1; off < SCAN_B / 32; off <<= 1) {
            int u = __shfl_up_sync(0xffu, s, off);
            if (t >= off) s += u;
        }
        wsum[t] = s;
    }
    __syncthreads();
    int warp = t >> 5;
    int excl = v - orig + ((warp > 0) ? wsum[warp - 1] : 0) + s_boff;
    if (i < N_NODES) {
        g_start[i]  = excl;
        g_cursor[i] = excl;
    }
}

// ---------------------------------------------------------
__global__ void scatter_kernel(const int* __restrict__ edge_dst) {
    int e = blockIdx.x * blockDim.x + threadIdx.x;
    if (e < N_EDGES) {
        int p = atomicAdd(&g_cursor[edge_dst[e]], 1);
        g_sorted[p] = e;
    }
}

// ---------------------------------------------------------
// Main: one block (128 threads) per destination node. Thread f owns channel f.
// (exact R2 structure — proven 403.5us)
__global__ __launch_bounds__(128, 4)
void main_kernel(const float* __restrict__ pos,
                 const float* __restrict__ eq,
                 const float* __restrict__ emb_table,
                 const float* __restrict__ w_rbf,
                 const float* __restrict__ b_rbf,
                 const int*   __restrict__ z,
                 const int*   __restrict__ edge_src,
                 float* __restrict__ out_emb,
                 float* __restrict__ out_eq) {
    int f = threadIdx.x;
    int node = blockIdx.x;

    int e0 = g_start[node];
    int e1 = __ldg(&g_start[node + 1]);
    int zi = __ldg(&z[node]);

    // per-thread w_rbf columns in registers (60 regs)
    float wr0[N_RBF], wr1[N_RBF], wr2[N_RBF];
#pragma unroll
    for (int k = 0; k < N_RBF; k++) {
        const float* row = w_rbf + k * F3;
        wr0[k] = row[f];
        wr1[k] = row[F_DIM + f];
        wr2[k] = row[2 * F_DIM + f];
    }
    const float br0 = b_rbf[f], br1 = b_rbf[F_DIM + f], br2 = b_rbf[2 * F_DIM + f];

    __shared__ float sh_rbf[128][N_RBF];
    __shared__ float sh_rd[128][3];    // rel * dist
    __shared__ int   sh_src[128];
    __shared__ int   sh_typ[128];
    __shared__ float sh_pos[3];

    int cnt = e1 - e0;

    if (f < 3) sh_pos[f] = pos[node * 3 + f];
    __syncthreads();
    const float pix = sh_pos[0], piy = sh_pos[1], piz = sh_pos[2];

    float acc0 = 0.f, aq0 = 0.f, aq1 = 0.f, aq2 = 0.f;

    for (int base = 0; base < cnt; base += 128) {
        int nch = min(128, cnt - base);
        // phase 1: one thread per edge computes geometry + RBF
        if (f < nch) {
            int e = g_sorted[e0 + base + f];
            int s = edge_src[e];
            sh_src[f] = s;
            sh_typ[f] = __ldg(&z[s]);
            float rx = pix - pos[s * 3 + 0];
            float ry = piy - pos[s * 3 + 1];
            float rz = piz - pos[s * 3 + 2];
            float dist = sqrtf(rx * rx + ry * ry + rz * rz);
            float inv  = 1.0f / dist;
            sh_rd[f][0] = rx * dist;
            sh_rd[f][1] = ry * dist;
            sh_rd[f][2] = rz * dist;
            float a = 3.14159265358979323846f * dist * (1.0f / CUTOFF);
            float s1, c1;
            sincosf(a, &s1, &c1);
            float twoc = 2.0f * c1;
            float sp = 0.0f, sc = s1;      // sin(0), sin(a)
#pragma unroll
            for (int k = 0; k < N_RBF; k++) {   // sin((k+1)a) via stable Chebyshev recurrence
                sh_rbf[f][k] = sc * inv;
                float nx = twoc * sc - sp;
                sp = sc; sc = nx;
            }
        }
        __syncthreads();
        // phase 2: all 128 threads accumulate over the chunk's edges
#pragma unroll 4
        for (int e = 0; e < nch; e++) {
            const float* ph = g_phi + sh_typ[e] * F3;
            int s = sh_src[e];
            const float* eqs = eq + (size_t)s * F3 + f * 3;
            float p0 = ph[f];
            float p1 = ph[F_DIM + f];
            float p2 = ph[2 * F_DIM + f];
            float eq0 = eqs[0], eq1 = eqs[1], eq2 = eqs[2];
            float W0 = br0, W1 = br1, W2 = br2;
#pragma unroll
            for (int k = 0; k < N_RBF; k++) {
                float r = sh_rbf[e][k];    // broadcast
                W0 = fmaf(r, wr0[k], W0);
                W1 = fmaf(r, wr1[k], W1);
                W2 = fmaf(r, wr2[k], W2);
            }
            float s1v = p1 * W1;
            float s2v = p2 * W2;
            acc0 = fmaf(p0, W0, acc0);
            aq0 = fmaf(eq0, s1v, fmaf(s2v, sh_rd[e][0], aq0));
            aq1 = fmaf(eq1, s1v, fmaf(s2v, sh_rd[e][1], aq1));
            aq2 = fmaf(eq2, s1v, fmaf(s2v, sh_rd[e][2], aq2));
        }
        __syncthreads();
    }

    // epilogue: out = input + delta (written exactly once, no atomics)
    out_emb[node * F_DIM + f] = emb_table[zi * F_DIM + f] + acc0;
    float*       oe = out_eq + (size_t)node * F3 + f * 3;
    const float* ei = eq     + (size_t)node * F3 + f * 3;
    oe[0] = ei[0] + aq0;
    oe[1] = ei[1] + aq1;
    oe[2] = ei[2] + aq2;
}

// ---------------------------------------------------------
extern "C" void kernel_launch(void* const* d_in, const int* in_sizes, int n_in,
                              void* d_out, int out_size) {
    const float* pos       = (const float*)d_in[0];
    const float* eq        = (const float*)d_in[1];
    const float* emb_table = (const float*)d_in[2];
    const float* w_phi1    = (const float*)d_in[3];
    const float* b_phi1    = (const float*)d_in[4];
    const float* w_phi2    = (const float*)d_in[5];
    const float* b_phi2    = (const float*)d_in[6];
    const float* w_rbf     = (const float*)d_in[7];
    const float* b_rbf     = (const float*)d_in[8];
    const int*   z         = (const int*)d_in[9];
    const int*   edge_src  = (const int*)d_in[10];
    const int*   edge_dst  = (const int*)d_in[11];

    float* out     = (float*)d_out;
    float* out_emb = out;                                  // [N, 128]
    float* out_eq  = out + (size_t)N_NODES * F_DIM;        // [N, 128, 3]

    init_kernel<<<ZERO_NB + N_TYPES, 128>>>(emb_table, w_phi1, b_phi1, w_phi2, b_phi2);
    hist_kernel<<<(N_EDGES + 255) / 256, 256>>>(edge_dst);
    scan1_kernel<<<SCAN_NB, SCAN_B>>>();
    scan23_kernel<<<SCAN_NB, SCAN_B>>>();
    scatter_kernel<<<(N_EDGES + 255) / 256, 256>>>(edge_dst);
    main_kernel<<<N_NODES, 128>>>(pos, eq, emb_table, w_rbf, b_rbf, z, edge_src,
                                  out_emb, out_eq);
}